// round 15
// baseline (speedup 1.0000x reference)
#include <cuda_runtime.h>
#include <cuda_fp16.h>
#include <mma.h>

using namespace nvcuda;

#define N_NODES     50000
#define N_PAD       50016
#define N_EDGES     800000
#define HIDDEN      128
#define F_IN        11
#define NUM_CLASSES 19
#define NUM_GRAPHS  2048

#define SCAN_B      256
#define N_SBLK      ((N_NODES + SCAN_B - 1) / SCAN_B)   // 196

// PDL: wait for predecessor grid's data before touching global memory.
#define GDC_WAIT() asm volatile("griddepcontrol.wait;" ::: "memory")

// ---- scratch ----
__device__ __align__(16) __half g_h16[N_NODES * HIDDEN];   // fp16 h' = dinv*h (layers 1,2)
__device__ __align__(16) __half g_agg16[N_PAD * HIDDEN];   // fp16 aggregated features
__device__ __align__(16) float g_agg11[N_NODES * 12];
__device__ __align__(16) float g_x11s[N_NODES * 12];       // x' = dinv*x, padded
__device__ float g_dinv[N_NODES];
__device__ int   g_counts[N_NODES];
__device__ int   g_fill[N_NODES];
__device__ int   g_rowptr[N_NODES + 1];
__device__ unsigned long long g_desc[N_SBLK];
__device__ int   g_col[N_EDGES];                           // 4B/edge
__device__ __align__(16) __half g_W2h[HIDDEN * HIDDEN];    // fp16 W2 [k][c]
__device__ __align__(16) __half g_W3h[HIDDEN * HIDDEN];    // fp16 W3 [k][c]
__device__ float g_pool[NUM_GRAPHS * HIDDEN];              // per-graph sums (layer 3)
__device__ int   g_gcnt[NUM_GRAPHS];

__device__ __forceinline__ int clampi(int v, int hi) {
    return v < 0 ? 0 : (v >= hi ? hi - 1 : v);
}

__device__ __forceinline__ void add_h2(float4& acc, uint2 v) {
    float2 fa = __half22float2(*(const __half2*)&v.x);
    float2 fb = __half22float2(*(const __half2*)&v.y);
    acc.x += fa.x; acc.y += fa.y; acc.z += fb.x; acc.w += fb.y;
}

// ---------------------------------------------------------------------------
__global__ void k_zero() {   // grid covers NUM_GRAPHS*HIDDEN = 262144
    int i = blockIdx.x * blockDim.x + threadIdx.x;
    if (i < NUM_GRAPHS * HIDDEN) g_pool[i] = 0.0f;
    if (i < N_NODES) { g_counts[i] = 0; g_fill[i] = 0; }
    if (i < NUM_GRAPHS) g_gcnt[i] = 0;
    if (i < N_SBLK) g_desc[i] = 0ULL;
}

// degree count: 4 edges per thread (int4 load, 4 independent atomics)
__global__ void k_deg(const int* __restrict__ ei) {
    GDC_WAIT();
    int q = blockIdx.x * blockDim.x + threadIdx.x;
    if (q >= N_EDGES / 4) return;
    int4 d = ((const int4*)(ei + N_EDGES))[q];
    atomicAdd(&g_counts[clampi(d.x, N_NODES)], 1);
    atomicAdd(&g_counts[clampi(d.y, N_NODES)], 1);
    atomicAdd(&g_counts[clampi(d.z, N_NODES)], 1);
    atomicAdd(&g_counts[clampi(d.w, N_NODES)], 1);
}

// fused: dinv + x pre-scale + per-graph counts + W2/W3 fp16 convert
__global__ void k_node_setup(const int* __restrict__ batch,
                             const float* __restrict__ x,
                             const float* __restrict__ W2,
                             const float* __restrict__ W3) {
    GDC_WAIT();
    int i = blockIdx.x * blockDim.x + threadIdx.x;
    if (i < N_NODES) {
        float di = rsqrtf((float)g_counts[i] + 1.0f);
        g_dinv[i] = di;
        atomicAdd(&g_gcnt[clampi(batch[i], NUM_GRAPHS)], 1);
#pragma unroll
        for (int f = 0; f < F_IN; f++)
            g_x11s[i * 12 + f] = x[i * F_IN + f] * di;
    }
    if (i < HIDDEN * HIDDEN) {
        g_W2h[i] = __float2half(W2[i]);
        g_W3h[i] = __float2half(W3[i]);
    }
}

// single-pass decoupled-lookback scan of g_counts -> g_rowptr
__global__ void __launch_bounds__(SCAN_B) k_scan_lb() {
    GDC_WAIT();
    __shared__ int s[SCAN_B];
    __shared__ unsigned int s_excl;
    int b = blockIdx.x;
    int t = threadIdx.x;
    volatile unsigned long long* vdesc = g_desc;

    int i = b * SCAN_B + t;
    int c = (i < N_NODES) ? g_counts[i] : 0;
    s[t] = c;
    __syncthreads();
    for (int off = 1; off < SCAN_B; off <<= 1) {
        int v = (t >= off) ? s[t - off] : 0;
        __syncthreads();
        s[t] += v;
        __syncthreads();
    }
    unsigned int total = (unsigned int)s[SCAN_B - 1];

    if (t < 32) {
        if (b == 0) {
            if (t == 0) {
                __threadfence();
                vdesc[0] = (2ULL << 62) | (unsigned long long)total;
                s_excl = 0;
            }
        } else {
            if (t == 0) {
                __threadfence();
                vdesc[b] = (1ULL << 62) | (unsigned long long)total;
            }
            unsigned long long sum = 0;
            int base = b - 1;
            while (true) {
                int idx = base - t;
                unsigned long long d = (idx >= 0) ? vdesc[idx] : (2ULL << 62);
                unsigned st = (unsigned)(d >> 62);
                unsigned long long val = d & 0xffffffffULL;
                unsigned pmask = __ballot_sync(0xffffffff, st == 2);
                unsigned zmask = __ballot_sync(0xffffffff, st == 0);
                if (pmask) {
                    int fp = __ffs(pmask) - 1;
                    if (zmask & ((fp ? ((1u << fp) - 1u) : 0u))) continue;
                    unsigned long long con = (t <= fp) ? val : 0ULL;
                    for (int off = 16; off; off >>= 1)
                        con += __shfl_down_sync(0xffffffff, con, off);
                    if (t == 0) sum += con;
                    break;
                } else {
                    if (zmask) continue;
                    unsigned long long con = val;
                    for (int off = 16; off; off >>= 1)
                        con += __shfl_down_sync(0xffffffff, con, off);
                    if (t == 0) sum += con;
                    base -= 32;
                }
            }
            if (t == 0) {
                __threadfence();
                vdesc[b] = (2ULL << 62) | ((sum + total) & 0xffffffffULL);
                s_excl = (unsigned int)sum;
            }
        }
    }
    __syncthreads();
    unsigned int excl = s_excl;
    if (i < N_NODES) g_rowptr[i] = (int)(excl + (unsigned int)s[t] - (unsigned int)c);
    if (i == N_NODES - 1) g_rowptr[N_NODES] = N_EDGES;
}

// scatter: 4 edges per thread (int4 loads, independent atomic chains)
__global__ void k_scatter(const int* __restrict__ ei) {
    GDC_WAIT();
    int q = blockIdx.x * blockDim.x + threadIdx.x;
    if (q >= N_EDGES / 4) return;
    int4 sv = ((const int4*)ei)[q];
    int4 dv = ((const int4*)(ei + N_EDGES))[q];
    int s0 = clampi(sv.x, N_NODES), d0 = clampi(dv.x, N_NODES);
    int s1 = clampi(sv.y, N_NODES), d1 = clampi(dv.y, N_NODES);
    int s2 = clampi(sv.z, N_NODES), d2 = clampi(dv.z, N_NODES);
    int s3 = clampi(sv.w, N_NODES), d3 = clampi(dv.w, N_NODES);
    int p0 = g_rowptr[d0] + atomicAdd(&g_fill[d0], 1);
    int p1 = g_rowptr[d1] + atomicAdd(&g_fill[d1], 1);
    int p2 = g_rowptr[d2] + atomicAdd(&g_fill[d2], 1);
    int p3 = g_rowptr[d3] + atomicAdd(&g_fill[d3], 1);
    g_col[p0] = s0;
    g_col[p1] = s1;
    g_col[p2] = s2;
    g_col[p3] = s3;
}

// aggregate pre-scaled x' (11-dim): agg[d] = dinv[d]*(sum x'[src] + x'[d])
__global__ void k_agg11() {
    GDC_WAIT();
    int gid = blockIdx.x * blockDim.x + threadIdx.x;
    int node = gid >> 4;
    int f = gid & 15;
    if (node >= N_NODES || f >= F_IN) return;
    int s = g_rowptr[node], e = g_rowptr[node + 1];
    float acc = 0.0f;
    int i = s;
    for (; i + 4 <= e; i += 4) {
        int c0 = g_col[i], c1 = g_col[i + 1], c2 = g_col[i + 2], c3 = g_col[i + 3];
        acc += g_x11s[c0 * 12 + f] + g_x11s[c1 * 12 + f]
             + g_x11s[c2 * 12 + f] + g_x11s[c3 * 12 + f];
    }
    for (; i < e; i++)
        acc += g_x11s[g_col[i] * 12 + f];
    acc += g_x11s[node * 12 + f];
    g_agg11[node * 12 + f] = acc * g_dinv[node];
}

// h1' = dinv * relu(agg11 @ W1 + b1) -> fp16
__global__ void k_gemm11(const float* __restrict__ W1, const float* __restrict__ b1) {
    GDC_WAIT();
    __shared__ float Ws[F_IN * HIDDEN];
    __shared__ float xs[32][12];
    __shared__ float sdinv[32];
    int t = threadIdx.x;
    int node0 = blockIdx.x * 32;
    for (int i = t; i < F_IN * HIDDEN; i += 128) Ws[i] = W1[i];
    for (int i = t; i < 32 * 12; i += 128) {
        int r = i / 12, f = i % 12;
        int n = node0 + r;
        xs[r][f] = (n < N_NODES) ? g_agg11[n * 12 + f] : 0.0f;
    }
    if (t < 32) sdinv[t] = (node0 + t < N_NODES) ? g_dinv[node0 + t] : 1.0f;
    __syncthreads();
    float bb = b1[t];
    for (int n = 0; n < 32; n++) {
        int node = node0 + n;
        if (node >= N_NODES) break;
        float acc = bb;
#pragma unroll
        for (int k = 0; k < F_IN; k++)
            acc += xs[n][k] * Ws[k * HIDDEN + t];
        g_h16[node * HIDDEN + t] = __float2half(fmaxf(acc, 0.0f) * sdinv[n]);
    }
}

// aggregate 128-dim pre-scaled fp16 h': warp per node, 8-deep MLP pipeline
__global__ void k_agg128() {
    GDC_WAIT();
    int gid = blockIdx.x * blockDim.x + threadIdx.x;
    int node = gid >> 5;
    int lane = gid & 31;
    if (node >= N_NODES) return;
    int s = g_rowptr[node], e = g_rowptr[node + 1];
    const uint2* __restrict__ h2 = (const uint2*)g_h16;
    float4 acc = make_float4(0.f, 0.f, 0.f, 0.f);
    int i = s;
    for (; i + 8 <= e; i += 8) {
        int c0 = g_col[i],     c1 = g_col[i + 1], c2 = g_col[i + 2], c3 = g_col[i + 3];
        int c4 = g_col[i + 4], c5 = g_col[i + 5], c6 = g_col[i + 6], c7 = g_col[i + 7];
        uint2 v0 = h2[c0 * 32 + lane];
        uint2 v1 = h2[c1 * 32 + lane];
        uint2 v2 = h2[c2 * 32 + lane];
        uint2 v3 = h2[c3 * 32 + lane];
        uint2 v4 = h2[c4 * 32 + lane];
        uint2 v5 = h2[c5 * 32 + lane];
        uint2 v6 = h2[c6 * 32 + lane];
        uint2 v7 = h2[c7 * 32 + lane];
        add_h2(acc, v0); add_h2(acc, v1); add_h2(acc, v2); add_h2(acc, v3);
        add_h2(acc, v4); add_h2(acc, v5); add_h2(acc, v6); add_h2(acc, v7);
    }
    for (; i + 4 <= e; i += 4) {
        int c0 = g_col[i], c1 = g_col[i + 1], c2 = g_col[i + 2], c3 = g_col[i + 3];
        uint2 v0 = h2[c0 * 32 + lane];
        uint2 v1 = h2[c1 * 32 + lane];
        uint2 v2 = h2[c2 * 32 + lane];
        uint2 v3 = h2[c3 * 32 + lane];
        add_h2(acc, v0); add_h2(acc, v1); add_h2(acc, v2); add_h2(acc, v3);
    }
    for (; i < e; i++)
        add_h2(acc, h2[g_col[i] * 32 + lane]);
    add_h2(acc, h2[node * 32 + lane]);
    float di = g_dinv[node];
    __half2 p = __floats2half2_rn(acc.x * di, acc.y * di);
    __half2 q = __floats2half2_rn(acc.z * di, acc.w * di);
    uint2 o;
    o.x = *(unsigned int*)&p;
    o.y = *(unsigned int*)&q;
    ((uint2*)g_agg16)[node * 32 + lane] = o;
}

// tensor-core GEMM: C[32x128] = agg16[32x128] @ W16[128x128] + bias
// which_w=0: W2, relu, write h' = dinv*relu -> fp16
// which_w=1: W3, accumulate per-graph sums into g_pool
__global__ void __launch_bounds__(256) k_gemm_wmma(const float* __restrict__ b, int which_w,
                                                   const int* __restrict__ batch) {
    GDC_WAIT();
    __shared__ float Cs[32][132];
    __shared__ float sdinv[32];
    __shared__ float sb[HIDDEN];
    __shared__ int   sgid[32];
    const __half* __restrict__ W16 = which_w ? g_W3h : g_W2h;
    int t = threadIdx.x;
    int wid = t >> 5;
    int wr = wid >> 2;
    int wc = wid & 3;
    int row0 = blockIdx.x * 32;

    if (t < 32) {
        int node = row0 + t;
        sdinv[t] = (node < N_NODES) ? g_dinv[node] : 1.0f;
        sgid[t] = (node < N_NODES) ? clampi(batch[node], NUM_GRAPHS) : -1;
    }
    if (t < HIDDEN) sb[t] = b[t];

    wmma::fragment<wmma::accumulator, 16, 16, 16, float> c0, c1;
    wmma::fill_fragment(c0, 0.0f);
    wmma::fill_fragment(c1, 0.0f);

    const __half* Abase = g_agg16 + (row0 + wr * 16) * HIDDEN;
#pragma unroll
    for (int k = 0; k < HIDDEN; k += 16) {
        wmma::fragment<wmma::matrix_a, 16, 16, 16, __half, wmma::row_major> af;
        wmma::load_matrix_sync(af, Abase + k, HIDDEN);
        wmma::fragment<wmma::matrix_b, 16, 16, 16, __half, wmma::row_major> b0f, b1f;
        wmma::load_matrix_sync(b0f, W16 + k * HIDDEN + wc * 32, HIDDEN);
        wmma::load_matrix_sync(b1f, W16 + k * HIDDEN + wc * 32 + 16, HIDDEN);
        wmma::mma_sync(c0, af, b0f, c0);
        wmma::mma_sync(c1, af, b1f, c1);
    }
    wmma::store_matrix_sync(&Cs[wr * 16][wc * 32], c0, 132, wmma::mem_row_major);
    wmma::store_matrix_sync(&Cs[wr * 16][wc * 32 + 16], c1, 132, wmma::mem_row_major);
    __syncthreads();

    if (which_w == 0) {
        int r = t >> 3;
        int cb = (t & 7) * 16;
        int node = row0 + r;
        if (node < N_NODES) {
            float di = sdinv[r];
#pragma unroll
            for (int j = 0; j < 16; j++) {
                float v = Cs[r][cb + j] + sb[cb + j];
                g_h16[node * HIDDEN + cb + j] = __float2half(fmaxf(v, 0.0f) * di);
            }
        }
    } else {
        int col = t & 127;
        int rbase = (t >> 7) * 16;
        float run = 0.0f;
        int cur = sgid[rbase];
#pragma unroll
        for (int j = 0; j < 16; j++) {
            int r = rbase + j;
            int g = sgid[r];
            if (g != cur) {
                if (cur >= 0) atomicAdd(&g_pool[cur * HIDDEN + col], run);
                run = 0.0f;
                cur = g;
            }
            if (g >= 0) run += Cs[r][col] + sb[col];
        }
        if (cur >= 0) atomicAdd(&g_pool[cur * HIDDEN + col], run);
    }
}

// final: mean + classifier head per graph
__global__ void __launch_bounds__(128) k_final(const float* __restrict__ Wl,
                                               const float* __restrict__ bl,
                                               float* __restrict__ out) {
    GDC_WAIT();
    __shared__ float ps[HIDDEN];
    int g = blockIdx.x;
    int t = threadIdx.x;
    float inv = 1.0f / fmaxf((float)g_gcnt[g], 1.0f);
    ps[t] = g_pool[g * HIDDEN + t] * inv;
    __syncthreads();
    if (t < NUM_CLASSES) {
        float o = bl[t];
#pragma unroll 8
        for (int h = 0; h < HIDDEN; h++)
            o += ps[h] * Wl[h * NUM_CLASSES + t];
        out[g * NUM_CLASSES + t] = o;
    }
}

// ---------------------------------------------------------------------------
extern "C" void kernel_launch(void* const* d_in, const int* in_sizes, int n_in,
                              void* d_out, int out_size) {
    const float* x     = (const float*)d_in[0];
    const int*   ei    = (const int*)d_in[1];
    const int*   batch = (const int*)d_in[2];
    const float* W1 = (const float*)d_in[3];
    const float* b1 = (const float*)d_in[4];
    const float* W2 = (const float*)d_in[5];
    const float* b2 = (const float*)d_in[6];
    const float* W3 = (const float*)d_in[7];
    const float* b3 = (const float*)d_in[8];
    const float* Wl = (const float*)d_in[9];
    const float* bl = (const float*)d_in[10];
    float* out = (float*)d_out;

    // PDL launcher: dependents may launch during predecessor's tail;
    // data dependency enforced by griddepcontrol.wait at kernel entry.
    auto launch = [](auto kern, dim3 grid, dim3 block, auto... args) {
        cudaLaunchConfig_t cfg = {};
        cfg.gridDim = grid;
        cfg.blockDim = block;
        cudaLaunchAttribute at[1];
        at[0].id = cudaLaunchAttributeProgrammaticStreamSerialization;
        at[0].val.programmaticStreamSerializationAllowed = 1;
        cfg.attrs = at;
        cfg.numAttrs = 1;
        cudaLaunchKernelEx(&cfg, kern, args...);
    };

    const int ZN = NUM_GRAPHS * HIDDEN;
    launch(k_zero, dim3((ZN + 255) / 256), dim3(256));
    launch(k_deg, dim3((N_EDGES / 4 + 255) / 256), dim3(256), ei);
    launch(k_scan_lb, dim3(N_SBLK), dim3(SCAN_B));
    launch(k_scatter, dim3((N_EDGES / 4 + 255) / 256), dim3(256), ei);
    launch(k_node_setup, dim3((N_NODES + 255) / 256), dim3(256), batch, x, W2, W3);
    launch(k_agg11, dim3((N_NODES * 16 + 255) / 256), dim3(256));
    launch(k_gemm11, dim3((N_NODES + 31) / 32), dim3(128), W1, b1);
    launch(k_agg128, dim3((N_NODES * 32 + 255) / 256), dim3(256));
    launch(k_gemm_wmma, dim3((N_NODES + 31) / 32), dim3(256), b2, 0, batch);
    launch(k_agg128, dim3((N_NODES * 32 + 255) / 256), dim3(256));
    launch(k_gemm_wmma, dim3((N_NODES + 31) / 32), dim3(256), b3, 1, batch);
    launch(k_final, dim3(NUM_GRAPHS), dim3(128), Wl, bl, out);
}

// round 16
// speedup vs baseline: 1.0649x; 1.0649x over previous
#include <cuda_runtime.h>
#include <cuda_fp16.h>
#include <mma.h>

using namespace nvcuda;

#define N_NODES     50000
#define N_PAD       50016
#define N_EDGES     800000
#define HIDDEN      128
#define F_IN        11
#define NUM_CLASSES 19
#define NUM_GRAPHS  2048

#define SCAN_B      256
#define N_SBLK      ((N_NODES + SCAN_B - 1) / SCAN_B)   // 196

// PDL: wait for predecessor grid's data before touching global memory.
#define GDC_WAIT() asm volatile("griddepcontrol.wait;" ::: "memory")

// ---- scratch ----
__device__ __align__(16) __half g_h16[N_NODES * HIDDEN];   // fp16 h' = dinv*h (layers 1,2)
__device__ __align__(16) __half g_agg16[N_PAD * HIDDEN];   // fp16 aggregated features
__device__ __align__(16) float g_agg11[N_NODES * 12];
__device__ __align__(16) float g_x11s[N_NODES * 12];       // x' = dinv*x, padded
__device__ float g_dinv[N_NODES];
__device__ int   g_counts[N_NODES];
__device__ int   g_epos[N_EDGES];                          // within-row slot from k_deg
__device__ int   g_rowptr[N_NODES + 1];
__device__ unsigned long long g_desc[N_SBLK];
__device__ int   g_col[N_EDGES];                           // 4B/edge
__device__ __align__(16) __half g_W2h[HIDDEN * HIDDEN];    // fp16 W2 [k][c]
__device__ __align__(16) __half g_W3h[HIDDEN * HIDDEN];    // fp16 W3 [k][c]
__device__ float g_pool[NUM_GRAPHS * HIDDEN];              // per-graph sums (layer 3)
__device__ int   g_gcnt[NUM_GRAPHS];

__device__ __forceinline__ int clampi(int v, int hi) {
    return v < 0 ? 0 : (v >= hi ? hi - 1 : v);
}

__device__ __forceinline__ void add_h2(float4& acc, uint2 v) {
    float2 fa = __half22float2(*(const __half2*)&v.x);
    float2 fb = __half22float2(*(const __half2*)&v.y);
    acc.x += fa.x; acc.y += fa.y; acc.z += fb.x; acc.w += fb.y;
}

// ---------------------------------------------------------------------------
__global__ void k_zero() {   // grid covers NUM_GRAPHS*HIDDEN = 262144
    int i = blockIdx.x * blockDim.x + threadIdx.x;
    if (i < NUM_GRAPHS * HIDDEN) g_pool[i] = 0.0f;
    if (i < N_NODES) g_counts[i] = 0;
    if (i < NUM_GRAPHS) g_gcnt[i] = 0;
    if (i < N_SBLK) g_desc[i] = 0ULL;
}

// degree count; atomic return value IS the within-row slot -> g_epos
__global__ void k_deg(const int* __restrict__ ei) {
    GDC_WAIT();
    int e = blockIdx.x * blockDim.x + threadIdx.x;
    if (e < N_EDGES) {
        int d = clampi(ei[N_EDGES + e], N_NODES);
        g_epos[e] = atomicAdd(&g_counts[d], 1);
    }
}

// fused: dinv + x pre-scale + per-graph counts + W2/W3 fp16 convert
__global__ void k_node_setup(const int* __restrict__ batch,
                             const float* __restrict__ x,
                             const float* __restrict__ W2,
                             const float* __restrict__ W3) {
    GDC_WAIT();
    int i = blockIdx.x * blockDim.x + threadIdx.x;
    if (i < N_NODES) {
        float di = rsqrtf((float)g_counts[i] + 1.0f);
        g_dinv[i] = di;
        atomicAdd(&g_gcnt[clampi(batch[i], NUM_GRAPHS)], 1);
#pragma unroll
        for (int f = 0; f < F_IN; f++)
            g_x11s[i * 12 + f] = x[i * F_IN + f] * di;
    }
    if (i < HIDDEN * HIDDEN) {
        g_W2h[i] = __float2half(W2[i]);
        g_W3h[i] = __float2half(W3[i]);
    }
}

// single-pass decoupled-lookback scan of g_counts -> g_rowptr
__global__ void __launch_bounds__(SCAN_B) k_scan_lb() {
    GDC_WAIT();
    __shared__ int s[SCAN_B];
    __shared__ unsigned int s_excl;
    int b = blockIdx.x;
    int t = threadIdx.x;
    volatile unsigned long long* vdesc = g_desc;

    int i = b * SCAN_B + t;
    int c = (i < N_NODES) ? g_counts[i] : 0;
    s[t] = c;
    __syncthreads();
    for (int off = 1; off < SCAN_B; off <<= 1) {
        int v = (t >= off) ? s[t - off] : 0;
        __syncthreads();
        s[t] += v;
        __syncthreads();
    }
    unsigned int total = (unsigned int)s[SCAN_B - 1];

    if (t < 32) {
        if (b == 0) {
            if (t == 0) {
                __threadfence();
                vdesc[0] = (2ULL << 62) | (unsigned long long)total;
                s_excl = 0;
            }
        } else {
            if (t == 0) {
                __threadfence();
                vdesc[b] = (1ULL << 62) | (unsigned long long)total;
            }
            unsigned long long sum = 0;
            int base = b - 1;
            while (true) {
                int idx = base - t;
                unsigned long long d = (idx >= 0) ? vdesc[idx] : (2ULL << 62);
                unsigned st = (unsigned)(d >> 62);
                unsigned long long val = d & 0xffffffffULL;
                unsigned pmask = __ballot_sync(0xffffffff, st == 2);
                unsigned zmask = __ballot_sync(0xffffffff, st == 0);
                if (pmask) {
                    int fp = __ffs(pmask) - 1;
                    if (zmask & ((fp ? ((1u << fp) - 1u) : 0u))) continue;
                    unsigned long long con = (t <= fp) ? val : 0ULL;
                    for (int off = 16; off; off >>= 1)
                        con += __shfl_down_sync(0xffffffff, con, off);
                    if (t == 0) sum += con;
                    break;
                } else {
                    if (zmask) continue;
                    unsigned long long con = val;
                    for (int off = 16; off; off >>= 1)
                        con += __shfl_down_sync(0xffffffff, con, off);
                    if (t == 0) sum += con;
                    base -= 32;
                }
            }
            if (t == 0) {
                __threadfence();
                vdesc[b] = (2ULL << 62) | ((sum + total) & 0xffffffffULL);
                s_excl = (unsigned int)sum;
            }
        }
    }
    __syncthreads();
    unsigned int excl = s_excl;
    if (i < N_NODES) g_rowptr[i] = (int)(excl + (unsigned int)s[t] - (unsigned int)c);
    if (i == N_NODES - 1) g_rowptr[N_NODES] = N_EDGES;
}

// scatter: atomic-free — slot precomputed in k_deg
__global__ void k_scatter(const int* __restrict__ ei) {
    GDC_WAIT();
    int e = blockIdx.x * blockDim.x + threadIdx.x;
    if (e >= N_EDGES) return;
    int s = clampi(ei[e], N_NODES);
    int d = clampi(ei[N_EDGES + e], N_NODES);
    g_col[g_rowptr[d] + g_epos[e]] = s;
}

// aggregate pre-scaled x' (11-dim): agg[d] = dinv[d]*(sum x'[src] + x'[d])
__global__ void k_agg11() {
    GDC_WAIT();
    int gid = blockIdx.x * blockDim.x + threadIdx.x;
    int node = gid >> 4;
    int f = gid & 15;
    if (node >= N_NODES || f >= F_IN) return;
    int s = g_rowptr[node], e = g_rowptr[node + 1];
    float acc = 0.0f;
    int i = s;
    for (; i + 4 <= e; i += 4) {
        int c0 = g_col[i], c1 = g_col[i + 1], c2 = g_col[i + 2], c3 = g_col[i + 3];
        acc += g_x11s[c0 * 12 + f] + g_x11s[c1 * 12 + f]
             + g_x11s[c2 * 12 + f] + g_x11s[c3 * 12 + f];
    }
    for (; i < e; i++)
        acc += g_x11s[g_col[i] * 12 + f];
    acc += g_x11s[node * 12 + f];
    g_agg11[node * 12 + f] = acc * g_dinv[node];
}

// h1' = dinv * relu(agg11 @ W1 + b1) -> fp16
__global__ void k_gemm11(const float* __restrict__ W1, const float* __restrict__ b1) {
    GDC_WAIT();
    __shared__ float Ws[F_IN * HIDDEN];
    __shared__ float xs[32][12];
    __shared__ float sdinv[32];
    int t = threadIdx.x;
    int node0 = blockIdx.x * 32;
    for (int i = t; i < F_IN * HIDDEN; i += 128) Ws[i] = W1[i];
    for (int i = t; i < 32 * 12; i += 128) {
        int r = i / 12, f = i % 12;
        int n = node0 + r;
        xs[r][f] = (n < N_NODES) ? g_agg11[n * 12 + f] : 0.0f;
    }
    if (t < 32) sdinv[t] = (node0 + t < N_NODES) ? g_dinv[node0 + t] : 1.0f;
    __syncthreads();
    float bb = b1[t];
    for (int n = 0; n < 32; n++) {
        int node = node0 + n;
        if (node >= N_NODES) break;
        float acc = bb;
#pragma unroll
        for (int k = 0; k < F_IN; k++)
            acc += xs[n][k] * Ws[k * HIDDEN + t];
        g_h16[node * HIDDEN + t] = __float2half(fmaxf(acc, 0.0f) * sdinv[n]);
    }
}

// aggregate 128-dim pre-scaled fp16 h': warp per node, 8-deep MLP pipeline
__global__ void k_agg128() {
    GDC_WAIT();
    int gid = blockIdx.x * blockDim.x + threadIdx.x;
    int node = gid >> 5;
    int lane = gid & 31;
    if (node >= N_NODES) return;
    int s = g_rowptr[node], e = g_rowptr[node + 1];
    const uint2* __restrict__ h2 = (const uint2*)g_h16;
    float4 acc = make_float4(0.f, 0.f, 0.f, 0.f);
    int i = s;
    for (; i + 8 <= e; i += 8) {
        int c0 = g_col[i],     c1 = g_col[i + 1], c2 = g_col[i + 2], c3 = g_col[i + 3];
        int c4 = g_col[i + 4], c5 = g_col[i + 5], c6 = g_col[i + 6], c7 = g_col[i + 7];
        uint2 v0 = h2[c0 * 32 + lane];
        uint2 v1 = h2[c1 * 32 + lane];
        uint2 v2 = h2[c2 * 32 + lane];
        uint2 v3 = h2[c3 * 32 + lane];
        uint2 v4 = h2[c4 * 32 + lane];
        uint2 v5 = h2[c5 * 32 + lane];
        uint2 v6 = h2[c6 * 32 + lane];
        uint2 v7 = h2[c7 * 32 + lane];
        add_h2(acc, v0); add_h2(acc, v1); add_h2(acc, v2); add_h2(acc, v3);
        add_h2(acc, v4); add_h2(acc, v5); add_h2(acc, v6); add_h2(acc, v7);
    }
    for (; i + 4 <= e; i += 4) {
        int c0 = g_col[i], c1 = g_col[i + 1], c2 = g_col[i + 2], c3 = g_col[i + 3];
        uint2 v0 = h2[c0 * 32 + lane];
        uint2 v1 = h2[c1 * 32 + lane];
        uint2 v2 = h2[c2 * 32 + lane];
        uint2 v3 = h2[c3 * 32 + lane];
        add_h2(acc, v0); add_h2(acc, v1); add_h2(acc, v2); add_h2(acc, v3);
    }
    for (; i < e; i++)
        add_h2(acc, h2[g_col[i] * 32 + lane]);
    add_h2(acc, h2[node * 32 + lane]);
    float di = g_dinv[node];
    __half2 p = __floats2half2_rn(acc.x * di, acc.y * di);
    __half2 q = __floats2half2_rn(acc.z * di, acc.w * di);
    uint2 o;
    o.x = *(unsigned int*)&p;
    o.y = *(unsigned int*)&q;
    ((uint2*)g_agg16)[node * 32 + lane] = o;
}

// tensor-core GEMM: C[32x128] = agg16[32x128] @ W16[128x128] + bias
// which_w=0: W2, relu, write h' = dinv*relu -> fp16
// which_w=1: W3, accumulate per-graph sums into g_pool
__global__ void __launch_bounds__(256) k_gemm_wmma(const float* __restrict__ b, int which_w,
                                                   const int* __restrict__ batch) {
    GDC_WAIT();
    __shared__ float Cs[32][132];
    __shared__ float sdinv[32];
    __shared__ float sb[HIDDEN];
    __shared__ int   sgid[32];
    const __half* __restrict__ W16 = which_w ? g_W3h : g_W2h;
    int t = threadIdx.x;
    int wid = t >> 5;
    int wr = wid >> 2;
    int wc = wid & 3;
    int row0 = blockIdx.x * 32;

    if (t < 32) {
        int node = row0 + t;
        sdinv[t] = (node < N_NODES) ? g_dinv[node] : 1.0f;
        sgid[t] = (node < N_NODES) ? clampi(batch[node], NUM_GRAPHS) : -1;
    }
    if (t < HIDDEN) sb[t] = b[t];

    wmma::fragment<wmma::accumulator, 16, 16, 16, float> c0, c1;
    wmma::fill_fragment(c0, 0.0f);
    wmma::fill_fragment(c1, 0.0f);

    const __half* Abase = g_agg16 + (row0 + wr * 16) * HIDDEN;
#pragma unroll
    for (int k = 0; k < HIDDEN; k += 16) {
        wmma::fragment<wmma::matrix_a, 16, 16, 16, __half, wmma::row_major> af;
        wmma::load_matrix_sync(af, Abase + k, HIDDEN);
        wmma::fragment<wmma::matrix_b, 16, 16, 16, __half, wmma::row_major> b0f, b1f;
        wmma::load_matrix_sync(b0f, W16 + k * HIDDEN + wc * 32, HIDDEN);
        wmma::load_matrix_sync(b1f, W16 + k * HIDDEN + wc * 32 + 16, HIDDEN);
        wmma::mma_sync(c0, af, b0f, c0);
        wmma::mma_sync(c1, af, b1f, c1);
    }
    wmma::store_matrix_sync(&Cs[wr * 16][wc * 32], c0, 132, wmma::mem_row_major);
    wmma::store_matrix_sync(&Cs[wr * 16][wc * 32 + 16], c1, 132, wmma::mem_row_major);
    __syncthreads();

    if (which_w == 0) {
        int r = t >> 3;
        int cb = (t & 7) * 16;
        int node = row0 + r;
        if (node < N_NODES) {
            float di = sdinv[r];
#pragma unroll
            for (int j = 0; j < 16; j++) {
                float v = Cs[r][cb + j] + sb[cb + j];
                g_h16[node * HIDDEN + cb + j] = __float2half(fmaxf(v, 0.0f) * di);
            }
        }
    } else {
        int col = t & 127;
        int rbase = (t >> 7) * 16;
        float run = 0.0f;
        int cur = sgid[rbase];
#pragma unroll
        for (int j = 0; j < 16; j++) {
            int r = rbase + j;
            int g = sgid[r];
            if (g != cur) {
                if (cur >= 0) atomicAdd(&g_pool[cur * HIDDEN + col], run);
                run = 0.0f;
                cur = g;
            }
            if (g >= 0) run += Cs[r][col] + sb[col];
        }
        if (cur >= 0) atomicAdd(&g_pool[cur * HIDDEN + col], run);
    }
}

// final: mean + classifier head per graph
__global__ void __launch_bounds__(128) k_final(const float* __restrict__ Wl,
                                               const float* __restrict__ bl,
                                               float* __restrict__ out) {
    GDC_WAIT();
    __shared__ float ps[HIDDEN];
    int g = blockIdx.x;
    int t = threadIdx.x;
    float inv = 1.0f / fmaxf((float)g_gcnt[g], 1.0f);
    ps[t] = g_pool[g * HIDDEN + t] * inv;
    __syncthreads();
    if (t < NUM_CLASSES) {
        float o = bl[t];
#pragma unroll 8
        for (int h = 0; h < HIDDEN; h++)
            o += ps[h] * Wl[h * NUM_CLASSES + t];
        out[g * NUM_CLASSES + t] = o;
    }
}

// ---------------------------------------------------------------------------
extern "C" void kernel_launch(void* const* d_in, const int* in_sizes, int n_in,
                              void* d_out, int out_size) {
    const float* x     = (const float*)d_in[0];
    const int*   ei    = (const int*)d_in[1];
    const int*   batch = (const int*)d_in[2];
    const float* W1 = (const float*)d_in[3];
    const float* b1 = (const float*)d_in[4];
    const float* W2 = (const float*)d_in[5];
    const float* b2 = (const float*)d_in[6];
    const float* W3 = (const float*)d_in[7];
    const float* b3 = (const float*)d_in[8];
    const float* Wl = (const float*)d_in[9];
    const float* bl = (const float*)d_in[10];
    float* out = (float*)d_out;

    // PDL launcher: dependents may launch during predecessor's tail;
    // data dependency enforced by griddepcontrol.wait at kernel entry.
    auto launch = [](auto kern, dim3 grid, dim3 block, auto... args) {
        cudaLaunchConfig_t cfg = {};
        cfg.gridDim = grid;
        cfg.blockDim = block;
        cudaLaunchAttribute at[1];
        at[0].id = cudaLaunchAttributeProgrammaticStreamSerialization;
        at[0].val.programmaticStreamSerializationAllowed = 1;
        cfg.attrs = at;
        cfg.numAttrs = 1;
        cudaLaunchKernelEx(&cfg, kern, args...);
    };

    const int ZN = NUM_GRAPHS * HIDDEN;
    launch(k_zero, dim3((ZN + 255) / 256), dim3(256));
    launch(k_deg, dim3((N_EDGES + 255) / 256), dim3(256), ei);
    launch(k_scan_lb, dim3(N_SBLK), dim3(SCAN_B));
    launch(k_scatter, dim3((N_EDGES + 255) / 256), dim3(256), ei);
    launch(k_node_setup, dim3((N_NODES + 255) / 256), dim3(256), batch, x, W2, W3);
    launch(k_agg11, dim3((N_NODES * 16 + 255) / 256), dim3(256));
    launch(k_gemm11, dim3((N_NODES + 31) / 32), dim3(128), W1, b1);
    launch(k_agg128, dim3((N_NODES * 32 + 255) / 256), dim3(256));
    launch(k_gemm_wmma, dim3((N_NODES + 31) / 32), dim3(256), b2, 0, batch);
    launch(k_agg128, dim3((N_NODES * 32 + 255) / 256), dim3(256));
    launch(k_gemm_wmma, dim3((N_NODES + 31) / 32), dim3(256), b3, 1, batch);
    launch(k_final, dim3(NUM_GRAPHS), dim3(128), Wl, bl, out);
}